// round 1
// baseline (speedup 1.0000x reference)
#include <cuda_runtime.h>
#include <cstdint>

// ---------------------------------------------------------------------------
// Blake2Cipher soft-hash, fp32, matching the JAX reference semantics.
//
// Key numeric facts exploited:
//  * jnp.mod(a, 2^64) for a>=0 == exact fmod; implemented exactly via
//    q = floor(a * 2^-64); r = fma(q, -2^64, a)  (both steps exact in fp32).
//  * All power-of-two scalings (*, /) are exact in fp32 (no overflow: max
//    intermediate ~2^112 << FLT_MAX).
//  * sigmoid via __expf + __fdividef: ~3e-7 error, far below tolerance given
//    the strongly contractive rot32/24/16 steps.
// ---------------------------------------------------------------------------

__device__ __forceinline__ float sigm(float z) {
    // sigmoid(z) = 1 / (1 + exp(-z))
    float e = __expf(-z);
    return __fdividef(1.0f, 1.0f + e);
}

__device__ __forceinline__ float soft_add(float x, float y) {
    float s = x + y;
    return s - sigm(10.0f * (s - 1.0f));
}

__device__ __forceinline__ float soft_xor(float x, float y) {
    float xs = sigm(10.0f * (x - 0.5f));
    float ys = sigm(10.0f * (y - 0.5f));
    float t1 = xs * (1.0f - ys);
    float t2 = (1.0f - xs) * ys;
    return __saturatef(t1 + t2 - t1 * t2);
}

// Exact a mod 2^64 for a >= 0 (fp32). Matches fmodf / jnp.mod bit-for-bit.
__device__ __forceinline__ float mod64(float a) {
    float q = floorf(a * 0x1p-64f);
    return fmaf(q, -0x1p64f, a);
}

template <int N>
__device__ __forceinline__ float rotr(float x) {
    // x_scaled = x * 2^64 (exact)
    float xs = x * 0x1p64f;
    // shifted_right = x_scaled / 2^N  (exact power-of-two scale)
    constexpr float inv_n = (float)(1.0 / (double)(1ull << N));
    float sr = xs * inv_n;
    // shifted_left = mod(x_scaled * 2^(64-N), 2^64)
    constexpr float mul_l = (float)((double)(1ull << (64 - N)));
    float sl = mod64(xs * mul_l);
    return mod64(sr + sl) * 0x1p-64f;
}

// One G mixing call on the register array v[16] with message words m[16].
#define GF(a, b, c, d, xi, yi)                                     \
    do {                                                           \
        v[a] = soft_add(v[a], v[b]);                               \
        v[a] = soft_add(v[a], m[xi]);                              \
        v[d] = soft_xor(v[d], v[a]);                               \
        v[d] = rotr<32>(v[d]);                                     \
        v[c] = soft_add(v[c], v[d]);                               \
        v[b] = soft_xor(v[b], v[c]);                               \
        v[b] = rotr<24>(v[b]);                                     \
        v[a] = soft_add(v[a], v[b]);                               \
        v[a] = soft_add(v[a], m[yi]);                              \
        v[d] = soft_xor(v[d], v[a]);                               \
        v[d] = rotr<16>(v[d]);                                     \
        v[c] = soft_add(v[c], v[d]);                               \
        v[b] = soft_xor(v[b], v[c]);                               \
        v[b] = rotr<63>(v[b]);                                     \
    } while (0)

// IV: int -> float32 (single cast) -> / 2^64 (exact scale).
#define IVF(x) ((float)(x##ull) * 0x1p-64f)

__global__ void __launch_bounds__(256)
blake2_soft_kernel(const float* __restrict__ msg, float* __restrict__ out, int batch) {
    int i = blockIdx.x * 256 + threadIdx.x;
    if (i >= batch) return;

    const float IV[8] = {
        IVF(7640891576956012808), IVF(13503953896175478587),
        IVF(4354685564936845355), IVF(11912009170470909681),
        IVF(5840696475078001361), IVF(11170449401992604703),
        IVF(2270897969802886507), IVF(6620516959819538809)
    };

    // Load 16 message words (64B per row) via 4x float4.
    float m[16];
    {
        const float4* mp = reinterpret_cast<const float4*>(msg) + (size_t)i * 4;
        float4 q0 = mp[0], q1 = mp[1], q2 = mp[2], q3 = mp[3];
        m[0] = q0.x;  m[1] = q0.y;  m[2] = q0.z;  m[3] = q0.w;
        m[4] = q1.x;  m[5] = q1.y;  m[6] = q1.z;  m[7] = q1.w;
        m[8] = q2.x;  m[9] = q2.y;  m[10] = q2.z; m[11] = q2.w;
        m[12] = q3.x; m[13] = q3.y; m[14] = q3.z; m[15] = q3.w;
    }

    float st[8];
#pragma unroll
    for (int j = 0; j < 8; j++) st[j] = IV[j];

    float v[16];
#pragma unroll 1   // keep rounds rolled: identical body, fits I$
    for (int r = 0; r < 10; r++) {
#pragma unroll
        for (int j = 0; j < 8; j++) { v[j] = st[j]; v[8 + j] = IV[j]; }

        GF(0, 4, 8, 12, 0, 1);
        GF(1, 5, 9, 13, 2, 3);
        GF(2, 6, 10, 14, 4, 5);
        GF(3, 7, 11, 15, 6, 7);
        GF(0, 5, 10, 15, 8, 9);
        GF(1, 6, 11, 12, 10, 11);
        GF(2, 7, 8, 13, 12, 13);
        GF(3, 4, 9, 14, 14, 15);

#pragma unroll
        for (int j = 0; j < 8; j++) st[j] = soft_xor(v[j], v[8 + j]);
    }

    float4* op = reinterpret_cast<float4*>(out) + (size_t)i * 2;
    op[0] = make_float4(st[0], st[1], st[2], st[3]);
    op[1] = make_float4(st[4], st[5], st[6], st[7]);
}

extern "C" void kernel_launch(void* const* d_in, const int* in_sizes, int n_in,
                              void* d_out, int out_size) {
    const float* msg = (const float*)d_in[0];
    float* out = (float*)d_out;
    int batch = in_sizes[0] / 16;
    int blocks = (batch + 255) / 256;
    blake2_soft_kernel<<<blocks, 256>>>(msg, out, batch);
}

// round 2
// speedup vs baseline: 1.6664x; 1.6664x over previous
#include <cuda_runtime.h>
#include <cstdint>

// ---------------------------------------------------------------------------
// Blake2Cipher soft-hash, fp32 — MUFU-optimized (R2).
// See theory: rot32/24/16 are exact single multiplies; tanh.approx on
// contraction-protected soft_xors; 4-way shared-reciprocal sigmoids.
// ---------------------------------------------------------------------------

#define K10   14.42695041f    // 10*log2(e)
#define KH     7.213475205f   // 5*log2(e)
#define SIG5   0.0066928509f  // sigmoid(-5)
#define SIG5S  0.066480567f   // d/dx sigmoid(10x-5) at x=0
#define TH25   0.98661430f    // tanh(2.5)
#define TH25S  0.13296110f    // d/dx tanh(5x-2.5) at x=0

__device__ __forceinline__ float ex2a(float x){ float r; asm("ex2.approx.f32 %0, %1;" : "=f"(r) : "f"(x)); return r; }
__device__ __forceinline__ float rcpa(float x){ float r; asm("rcp.approx.f32 %0, %1;" : "=f"(r) : "f"(x)); return r; }
__device__ __forceinline__ float tanha(float x){ float r; asm("tanh.approx.f32 %0, %1;" : "=f"(r) : "f"(x)); return r; }

// 4 independent sigmoids sharing one (NR-refined) reciprocal.
// w[q] = -z*log2(e) already; sg[q] = 1/(1+2^w[q]).
__device__ __forceinline__ void sig4_from_w(const float w[4], float sg[4]) {
    float e0 = ex2a(w[0]), e1 = ex2a(w[1]), e2 = ex2a(w[2]), e3 = ex2a(w[3]);
    float d0 = 1.0f + e0, d1 = 1.0f + e1, d2 = 1.0f + e2, d3 = 1.0f + e3;
    float p01 = d0 * d1, p23 = d2 * d3;
    float P = p01 * p23;
    float r0 = rcpa(P);
    float er = fmaf(-P, r0, 1.0f);
    float R  = fmaf(r0, er, r0);        // Newton: ~0.5 ulp reciprocal
    float R01 = R * p23, R23 = R * p01; // 1/(d0*d1), 1/(d2*d3)
    sg[0] = R01 * d1; sg[1] = R01 * d0;
    sg[2] = R23 * d3; sg[3] = R23 * d2;
}

// Baseline-accurate scalar sigmoid (same numerics as R1, which passed @2.5e-5)
__device__ __forceinline__ float sigm1(float z) {
    float e = __expf(-z);
    return __fdividef(1.0f, 1.0f + e);
}

__device__ __forceinline__ float soft_xor_exact(float x, float y) {
    float xs = sigm1(10.0f * (x - 0.5f));
    float ys = sigm1(10.0f * (y - 0.5f));
    float t1 = xs * (1.0f - ys);
    float t2 = (1.0f - xs) * ys;
    return __saturatef((t1 + t2) - t1 * t2);
}

// soft_xor in tanh form: 0.5*(1 - tx*ty) - (1-tx^2)(1-ty^2)/16
__device__ __forceinline__ float sxt_comb(float tx, float ty) {
    float p  = tx * ty;
    float a0 = fmaf(p, -0.5f, 0.5f);
    float q1 = fmaf(-tx, tx, 1.0f);
    float q2 = fmaf(-ty, ty, 1.0f);
    return __saturatef(fmaf(q1 * q2, -0.0625f, a0));
}

// Exact rotr<63> (proven to match the reference fp32 mod arithmetic bit-for-bit)
__device__ __forceinline__ float rot63(float x) {
    float t2  = x + x;                       // shifted_right = 2x (exact)
    float xs2 = x * 0x1p65f;                 // x_scaled * 2 (exact)
    float qq  = floorf(t2);                  // floor(v / 2^64)
    float sl  = fmaf(qq, -0x1p64f, xs2);     // exact remainder
    float sum = t2 + sl;                     // same fp32 rounding as reference
    return sum * 0x1p-64f;
}

// 4 interleaved G calls (column step: DIAG=false, diagonal step: DIAG=true)
template <bool DIAG>
__device__ __forceinline__ void G4(float v[16], const float m[16]) {
#define IA(q) (q)
#define IB(q) (DIAG ? 4 + (((q) + 1) & 3) : 4 + (q))
#define IC(q) (DIAG ? 8 + (((q) + 2) & 3) : 8 + (q))
#define ID(q) (DIAG ? 12 + (((q) + 3) & 3) : 12 + (q))
#define IX(q) (DIAG ? 8 + 2 * (q) : 2 * (q))
#define IY(q) (DIAG ? 9 + 2 * (q) : 2 * (q) + 1)

#define SA4(TIDX, UEXPR)                                                  \
    {                                                                     \
        float s_[4], w_[4], g_[4];                                        \
        _Pragma("unroll") for (int q = 0; q < 4; q++) {                   \
            s_[q] = v[TIDX] + (UEXPR);                                    \
        }                                                                 \
        _Pragma("unroll") for (int q = 0; q < 4; q++) {                   \
            w_[q] = fmaf(s_[q], -K10, K10);                               \
        }                                                                 \
        sig4_from_w(w_, g_);                                              \
        _Pragma("unroll") for (int q = 0; q < 4; q++) {                   \
            v[TIDX] = s_[q] - g_[q];                                      \
        }                                                                 \
    }

    // S1: a = sa(a, b)
    SA4(IA(q), v[IB(q)]);
    // S2: a = sa(a, m[x])
    SA4(IA(q), m[IX(q)]);
    // S3: d = sx(d, a); rot32 -> exact *2^-32. Protected (error * 2^-32).
#pragma unroll
    for (int q = 0; q < 4; q++) {
        float dv = v[ID(q)];
        // diagonal step: d is a rot16 output (<= 1.6e-5): linearize tanh
        float tx = DIAG ? fmaf(dv, TH25S, -TH25) : tanha(fmaf(dv, 5.0f, -2.5f));
        float ty = tanha(fmaf(v[IA(q)], 5.0f, -2.5f));
        v[ID(q)] = sxt_comb(tx, ty) * 0x1p-32f;
    }
    // S4: c = sa(c, d)
    SA4(IC(q), v[ID(q)]);
    // S5: b = sx(b, c); rot24 -> exact *2^-24. Protected.
#pragma unroll
    for (int q = 0; q < 4; q++) {
        float tx = tanha(fmaf(v[IB(q)], 5.0f, -2.5f));
        float ty = tanha(fmaf(v[IC(q)], 5.0f, -2.5f));
        v[IB(q)] = sxt_comb(tx, ty) * 0x1p-24f;
    }
    // S6: a = sa(a, b)
    SA4(IA(q), v[IB(q)]);
    // S7: a = sa(a, m[y])
    SA4(IA(q), m[IY(q)]);
    // S8: d = sx(d, a); rot16 -> exact *2^-16. Protected; d is rot32-out (tiny).
#pragma unroll
    for (int q = 0; q < 4; q++) {
        float tx = fmaf(v[ID(q)], TH25S, -TH25);
        float ty = tanha(fmaf(v[IA(q)], 5.0f, -2.5f));
        v[ID(q)] = sxt_comb(tx, ty) * 0x1p-16f;
    }
    // S9: c = sa(c, d)
    SA4(IC(q), v[ID(q)]);
    // S10: b = sx(b, c); rot63. FLIP-SENSITIVE: ys accurate exp; xs of the
    // tiny rot24-out b is linearized (error < 1e-9, better than baseline).
    {
        float wy[4], ys[4];
#pragma unroll
        for (int q = 0; q < 4; q++) wy[q] = fmaf(v[IC(q)], -K10, KH);
        sig4_from_w(wy, ys);
#pragma unroll
        for (int q = 0; q < 4; q++) {
            float xs = fmaf(v[IB(q)], SIG5S, SIG5);
            float t1 = xs * (1.0f - ys[q]);
            float t2 = (1.0f - xs) * ys[q];
            float f  = __saturatef((t1 + t2) - t1 * t2);
            v[IB(q)] = rot63(f);
        }
    }
#undef SA4
#undef IA
#undef IB
#undef IC
#undef ID
#undef IX
#undef IY
}

#define IVF(x) ((float)(x##ull) * 0x1p-64f)

__global__ void __launch_bounds__(128, 6)
blake2_soft_kernel(const float* __restrict__ msg, float* __restrict__ out, int batch) {
    int i = blockIdx.x * 128 + threadIdx.x;
    if (i >= batch) return;

    const float IV[8] = {
        IVF(7640891576956012808), IVF(13503953896175478587),
        IVF(4354685564936845355), IVF(11912009170470909681),
        IVF(5840696475078001361), IVF(11170449401992604703),
        IVF(2270897969802886507), IVF(6620516959819538809)
    };

    float m[16];
    {
        const float4* mp = reinterpret_cast<const float4*>(msg) + (size_t)i * 4;
        float4 q0 = mp[0], q1 = mp[1], q2 = mp[2], q3 = mp[3];
        m[0] = q0.x;  m[1] = q0.y;  m[2] = q0.z;  m[3] = q0.w;
        m[4] = q1.x;  m[5] = q1.y;  m[6] = q1.z;  m[7] = q1.w;
        m[8] = q2.x;  m[9] = q2.y;  m[10] = q2.z; m[11] = q2.w;
        m[12] = q3.x; m[13] = q3.y; m[14] = q3.z; m[15] = q3.w;
    }

    float v[16];
#pragma unroll
    for (int j = 0; j < 8; j++) v[j] = IV[j];

#pragma unroll 1
    for (int r = 0; r < 10; r++) {
#pragma unroll
        for (int j = 0; j < 8; j++) v[8 + j] = IV[j];

        G4<false>(v, m);  // column step: 4 independent G's
        G4<true>(v, m);   // diagonal step: 4 independent G's

        // state = soft_xor(v[j], v[8+j]) — flip-sensitive, keep accurate.
#pragma unroll
        for (int j = 0; j < 4; j++)
            v[j] = soft_xor_exact(v[j], v[8 + j]);
#pragma unroll
        for (int j = 4; j < 8; j++) {
            // v[8+j] = d-word = rot16 output (<=1.6e-5): linear sigmoid exact
            float xs = sigm1(10.0f * (v[j] - 0.5f));
            float ys = fmaf(v[8 + j], SIG5S, SIG5);
            float t1 = xs * (1.0f - ys);
            float t2 = (1.0f - xs) * ys;
            v[j] = __saturatef((t1 + t2) - t1 * t2);
        }
    }

    float4* op = reinterpret_cast<float4*>(out) + (size_t)i * 2;
    op[0] = make_float4(v[0], v[1], v[2], v[3]);
    op[1] = make_float4(v[4], v[5], v[6], v[7]);
}

extern "C" void kernel_launch(void* const* d_in, const int* in_sizes, int n_in,
                              void* d_out, int out_size) {
    const float* msg = (const float*)d_in[0];
    float* out = (float*)d_out;
    int batch = in_sizes[0] / 16;
    int blocks = (batch + 127) / 128;
    blake2_soft_kernel<<<blocks, 128>>>(msg, out, batch);
}